// round 2
// baseline (speedup 1.0000x reference)
#include <cuda_runtime.h>
#include <math.h>
#include <stdint.h>

// Problem constants
#define B_ROWS   131072
#define NM       6
#define NP       30
#define WARPS    8
#define GRID     2048
#define ROWS_PER_WARP (B_ROWS / (GRID * WARPS))   // 8

// Global accumulators:
// 0 num_cls, 1 mgn_sum, 2 reg_loss, 3 num_reg,
// 4 a6x, 5 a6y, 6 f6x, 7 f6y, 8 a1x, 9 a1y, 10 f1x, 11 f1y
__device__ double g_acc[12];

__global__ void zero_acc_kernel() {
    if (threadIdx.x < 12) g_acc[threadIdx.x] = 0.0;
}

struct __align__(16) WSm {
    float reg[360];   // one row of reg [6,30,2]
    float gt[64];     // 60 used
    float cosv[32];   // cos(theta_t)
    float sinv[32];   // sin(theta_t)
    float hasw[32];   // has[t] as float
};

__device__ __forceinline__ float warp_sum(float v) {
#pragma unroll
    for (int o = 16; o; o >>= 1) v += __shfl_xor_sync(0xffffffffu, v, o);
    return v;
}

__global__ void __launch_bounds__(256) loss_main(
    const float* __restrict__ reg,
    const float* __restrict__ cls,
    const float* __restrict__ gt,
    const void*  __restrict__ has)
{
    __shared__ WSm ws[WARPS];
    __shared__ double blk[12];

    const int lane = threadIdx.x & 31;
    const int warp = threadIdx.x >> 5;
    if (threadIdx.x < 12) blk[threadIdx.x] = 0.0;
    __syncthreads();

    // ---- detect storage width of the bool array `has` ----
    // uint8 bools (all-true dataset) -> first word 0x01010101
    // int32 bools                     -> first word 0x00000001
    // float32 bools                   -> first word 0x3F800000
    const unsigned w0 = *((const unsigned*)has);
    const int hmode = (w0 == 0x3F800000u) ? 2 : ((w0 == 1u) ? 1 : 0);

    WSm& S = ws[warp];
    const int wg = blockIdx.x * WARPS + warp;

    // per-lane partial sums (fp32; small magnitudes per lane)
    float a_numcls = 0.f, a_mgn = 0.f, a_regl = 0.f, a_numreg = 0.f;
    float a6x = 0.f, a6y = 0.f, f6x = 0.f, f6y = 0.f;
    float a1x = 0.f, a1y = 0.f, f1x = 0.f, f1y = 0.f;

    for (int it = 0; it < ROWS_PER_WARP; ++it) {
        const int row = wg + it * (GRID * WARPS);

        // ---- coalesced staging: reg row (1440B) + gt row (240B) ----
        const float4* rp = (const float4*)(reg + (size_t)row * 360);
#pragma unroll
        for (int i = 0; i < 3; i++) {
            int idx = lane + 32 * i;
            if (idx < 90) ((float4*)S.reg)[idx] = rp[idx];
        }
        if (lane < 15)
            ((float4*)S.gt)[lane] = ((const float4*)(gt + (size_t)row * 60))[lane];

        // ---- has / last index / valid ----
        float hv = 0.f;
        if (lane < NP) {
            size_t hidx = (size_t)row * NP + lane;
            if (hmode == 0)      hv = ((const unsigned char*)has)[hidx] ? 1.0f : 0.0f;
            else if (hmode == 1) hv = ((const int*)has)[hidx] ? 1.0f : 0.0f;
            else                 hv = (((const float*)has)[hidx] != 0.0f) ? 1.0f : 0.0f;
        }
        float lastv = (lane < NP) ? hv + (0.1f * (float)lane) / 30.0f : -1e30f;
        int   lidx  = (lane < NP) ? lane : 1000;
        {
            float mv = lastv; int mi = lidx;
#pragma unroll
            for (int o = 16; o; o >>= 1) {
                float v2 = __shfl_xor_sync(0xffffffffu, mv, o);
                int   i2 = __shfl_xor_sync(0xffffffffu, mi, o);
                if (v2 > mv || (v2 == mv && i2 < mi)) { mv = v2; mi = i2; }
            }
            lidx = mi; lastv = mv;
        }
        const int   last   = lidx;
        const bool  valid  = lastv > 1.0f;
        const float validf = valid ? 1.0f : 0.0f;

        unsigned bal = __ballot_sync(0xffffffffu, (lane < NP) && (hv > 0.f));
        if (lane == 0) a_numreg += validf * (float)__popc(bal);
        if (lane < NP) S.hasw[lane] = hv;

        __syncwarp();

        // ---- moving flag ----
        const float g0x = S.gt[0],  g0y = S.gt[1];
        const float gLx = S.gt[58], gLy = S.gt[59];
        const float mdx = g0x - gLx, mdy = g0y - gLy;
        const bool moving = sqrtf(mdx * mdx + mdy * mdy) > 2.0f;

        // ---- heading rotation (trig-free), lane t computes cos/sin of theta_t ----
        if (lane < NP) {
            float ct = 1.f, st = 0.f;
            if (moving) {
                // segment j: unit vector + "angle is exactly zero" flag (atan2 semantics)
                auto unitf = [&](int j, float& c, float& s, bool& za) {
                    float dx = S.gt[2 * j + 2] - S.gt[2 * j];
                    float dy = S.gt[2 * j + 3] - S.gt[2 * j + 1];
                    float rr = dx * dx + dy * dy;
                    za = (dy == 0.0f) && (dx >= 0.0f);
                    if (rr == 0.f) { c = 1.f; s = 0.f; }
                    else { float inv = rsqrtf(rr); c = dx * inv; s = dy * inv; }
                };
                if (lane == 0) {
                    float c, s; bool za; unitf(0, c, s, za);
                    ct = c; st = -s;                      // theta = -seg0
                } else if (lane == NP - 1) {
                    float c, s; bool za; unitf(NP - 2, c, s, za);
                    ct = c; st = -s;                      // theta = -seg28
                } else {
                    float ca, sa, cb, sb; bool za, zb;
                    unitf(lane,     ca, sa, za);          // fwd
                    unitf(lane - 1, cb, sb, zb);          // bwd
                    if (za || zb) {
                        // theta = -(a+b): angle-sum formulas
                        ct = ca * cb - sa * sb;
                        st = -(sa * cb + ca * sb);
                    } else {
                        // theta = -(a+b)/2 (mod pi; pi-flip is abs-invariant)
                        float hx = ca + cb, hy = sa + sb;
                        float dxx = ca - cb, dyy = sa - sb;
                        float h2 = hx * hx + hy * hy;
                        float d2 = dxx * dxx + dyy * dyy;
                        if (h2 >= d2) {
                            float inv = rsqrtf(h2);
                            ct = hx * inv; st = -(hy * inv);
                        } else {
                            // u - v is perpendicular to the bisector
                            float inv = rsqrtf(d2);
                            ct = dyy * inv; st = dxx * inv;
                        }
                    }
                }
            }
            S.cosv[lane] = ct;
            S.sinv[lane] = st;
        }

        // ---- dist to gt at last index; min mode; cls argmax ----
        float myc = 0.f, distm = 1e30f;
        if (lane < NM) {
            myc = cls[(size_t)row * NM + lane];
            float rx = S.reg[lane * 60 + last * 2];
            float ry = S.reg[lane * 60 + last * 2 + 1];
            float gx = S.gt[2 * last], gy = S.gt[2 * last + 1];
            float ddx = rx - gx, ddy = ry - gy;
            distm = sqrtf(ddx * ddx + ddy * ddy);
        }
        int min_idx; float min_dist;
        {
            float dv = distm; int di = (lane < NM) ? lane : 1000;
#pragma unroll
            for (int o = 16; o; o >>= 1) {
                float v2 = __shfl_xor_sync(0xffffffffu, dv, o);
                int   i2 = __shfl_xor_sync(0xffffffffu, di, o);
                if (v2 < dv || (v2 == dv && i2 < di)) { dv = v2; di = i2; }
            }
            min_idx = di; min_dist = dv;
        }
        int top1;
        {
            float cv = (lane < NM) ? myc : -1e30f;
            int   ci = (lane < NM) ? lane : 1000;
#pragma unroll
            for (int o = 16; o; o >>= 1) {
                float v2 = __shfl_xor_sync(0xffffffffu, cv, o);
                int   i2 = __shfl_xor_sync(0xffffffffu, ci, o);
                if (v2 > cv || (v2 == cv && i2 < ci)) { cv = v2; ci = i2; }
            }
            top1 = ci;
        }
        const float cls_min = __shfl_sync(0xffffffffu, myc, min_idx);
        if (lane < NM) {
            float mgn = cls_min - myc;
            bool m01 = (min_dist < 2.0f) && ((distm - min_dist) > 0.2f) && valid;
            if (m01 && (mgn < 0.2f)) { a_numcls += 1.0f; a_mgn += mgn; }
        }

        __syncwarp();  // cosv/sinv visible to all lanes

        // ---- main (mode, t) sweep: 180 pairs over 32 lanes ----
#pragma unroll
        for (int k = 0; k < 6; k++) {
            int p = k * 32 + lane;
            if (p < NM * NP) {
                int m = p / NP;
                int t = p - m * NP;
                float rx = S.reg[m * 60 + t * 2];
                float ry = S.reg[m * 60 + t * 2 + 1];
                float gx = S.gt[2 * t], gy = S.gt[2 * t + 1];
                float dx = fabsf(gx - rx);
                float dy = fabsf(gy - ry);
                float c = S.cosv[t], s = S.sinv[t];
                float ex = fabsf(c * dx - s * dy);
                float ey = fabsf(s * dx + c * dy);
                a6x += ex; a6y += ey;
                if (t == NP - 1) { f6x += ex; f6y += ey; }
                if (m == top1) {
                    a1x += ex; a1y += ey;
                    if (t == NP - 1) { f1x += ex; f1y += ey; }
                }
                if (m == min_idx) {
                    float w = S.hasw[t] * validf;
                    float slx = (dx < 1.f) ? 0.5f * dx * dx : dx - 0.5f;
                    float sly = (dy < 1.f) ? 0.5f * dy * dy : dy - 0.5f;
                    a_regl += (slx + sly) * w;
                }
            }
        }
        __syncwarp();  // WAR before next iteration's staging
    }

    // ---- reduction: warp -> shared double -> global double ----
    a_numcls = warp_sum(a_numcls);
    a_mgn    = warp_sum(a_mgn);
    a_regl   = warp_sum(a_regl);
    a_numreg = warp_sum(a_numreg);
    a6x = warp_sum(a6x); a6y = warp_sum(a6y);
    f6x = warp_sum(f6x); f6y = warp_sum(f6y);
    a1x = warp_sum(a1x); a1y = warp_sum(a1y);
    f1x = warp_sum(f1x); f1y = warp_sum(f1y);

    if (lane == 0) {
        atomicAdd(&blk[0],  (double)a_numcls);
        atomicAdd(&blk[1],  (double)a_mgn);
        atomicAdd(&blk[2],  (double)a_regl);
        atomicAdd(&blk[3],  (double)a_numreg);
        atomicAdd(&blk[4],  (double)a6x);
        atomicAdd(&blk[5],  (double)a6y);
        atomicAdd(&blk[6],  (double)f6x);
        atomicAdd(&blk[7],  (double)f6y);
        atomicAdd(&blk[8],  (double)a1x);
        atomicAdd(&blk[9],  (double)a1y);
        atomicAdd(&blk[10], (double)f1x);
        atomicAdd(&blk[11], (double)f1y);
    }
    __syncthreads();
    if (threadIdx.x < 12) atomicAdd(&g_acc[threadIdx.x], blk[threadIdx.x]);
}

__global__ void finalize_kernel(float* out) {
    if (threadIdx.x == 0) {
        double num_cls  = g_acc[0];
        double mgn_sum  = g_acc[1];
        double reg_loss = g_acc[2];
        double num_reg  = g_acc[3];
        double cls_loss = 1.0 * (0.2 * num_cls - mgn_sum);
        double loss = cls_loss / (num_cls + 1e-10) + reg_loss / (num_reg + 1e-10);
        out[0]  = (float)loss;
        out[1]  = (float)cls_loss;
        out[2]  = (float)num_cls;
        out[3]  = (float)reg_loss;
        out[4]  = (float)num_reg;
        out[5]  = (float)g_acc[4];
        out[6]  = (float)g_acc[5];
        out[7]  = (float)g_acc[6];
        out[8]  = (float)g_acc[7];
        out[9]  = (float)(6.0 * (double)B_ROWS * 30.0);
        out[10] = (float)(6.0 * (double)B_ROWS);
        out[11] = (float)g_acc[8];
        out[12] = (float)g_acc[9];
        out[13] = (float)g_acc[10];
        out[14] = (float)g_acc[11];
        out[15] = (float)((double)B_ROWS * 30.0);
        out[16] = (float)B_ROWS;
    }
}

extern "C" void kernel_launch(void* const* d_in, const int* in_sizes, int n_in,
                              void* d_out, int out_size) {
    // Map inputs by element count (robust to metadata ordering):
    //   reg: 47,185,920   gt: 7,864,320   has: 3,932,160   cls: 786,432
    const float* reg = nullptr;
    const float* cls = nullptr;
    const float* gt  = nullptr;
    const void*  has = nullptr;
    for (int i = 0; i < n_in; i++) {
        long long n = in_sizes[i];
        if (n == (long long)B_ROWS * NM * NP * 2)      reg = (const float*)d_in[i];
        else if (n == (long long)B_ROWS * NP * 2)      gt  = (const float*)d_in[i];
        else if (n == (long long)B_ROWS * NP)          has = d_in[i];
        else if (n == (long long)B_ROWS * NM)          cls = (const float*)d_in[i];
    }
    float* out = (float*)d_out;

    zero_acc_kernel<<<1, 32>>>();
    loss_main<<<GRID, 256>>>(reg, cls, gt, has);
    finalize_kernel<<<1, 32>>>(out);
}

// round 3
// speedup vs baseline: 1.0123x; 1.0123x over previous
#include <cuda_runtime.h>
#include <math.h>
#include <stdint.h>

#define B_ROWS   131072
#define NM       6
#define NP       30
#define WARPS    8
#define GRID     2048
#define RPW      (B_ROWS / (GRID * WARPS))   // 8 rows per warp

// Global accumulators:
// 0 num_cls, 1 mgn_sum, 2 reg_loss, 3 num_reg,
// 4 a6x, 5 a6y, 6 f6x, 7 f6y, 8 a1x, 9 a1y, 10 f1x, 11 f1y
__device__ double g_acc[12];
__device__ unsigned int g_done;

struct __align__(16) SmBuf {
    float gt[64];     // 60 used
    float cosv[32];
    float sinv[32];
    float hasw[32];
};

__device__ __forceinline__ float warp_sum(float v) {
#pragma unroll
    for (int o = 16; o; o >>= 1) v += __shfl_xor_sync(0xffffffffu, v, o);
    return v;
}

__global__ void __launch_bounds__(256) loss_main(
    const float* __restrict__ reg,
    const float* __restrict__ cls,
    const float* __restrict__ gt,
    const void*  __restrict__ has,
    float* __restrict__ out)
{
    __shared__ SmBuf sb[WARPS][2];
    __shared__ float sdist[WARPS][8];
    __shared__ double blk[12];

    const int lane = threadIdx.x & 31;
    const int warp = threadIdx.x >> 5;
    if (threadIdx.x < 12) blk[threadIdx.x] = 0.0;
    __syncthreads();

    // detect storage width of bool array `has`
    const unsigned w0 = *((const unsigned*)has);
    const int hmode = (w0 == 0x3F800000u) ? 2 : ((w0 == 1u) ? 1 : 0);

    const int wg = blockIdx.x * WARPS + warp;

    // ---- lane-constant pair mapping: lane owns float4s {lane, lane+32, lane+64} ----
    // float4 j holds pairs 2j, 2j+1 of the 180 (mode,t) pairs
    int tk[6], mk[6];
    bool pv[6];
#pragma unroll
    for (int k = 0; k < 6; k++) {
        int q = 2 * lane + ((k >> 1) * 64) + (k & 1);
        pv[k] = q < 180;
        mk[k] = q / 30;
        tk[k] = q - mk[k] * 30;
    }

    // per-lane partials
    float a_numcls = 0.f, a_mgn = 0.f, a_regl = 0.f, a_numreg = 0.f;
    float a6x = 0.f, a6y = 0.f, f6x = 0.f, f6y = 0.f;
    float a1x = 0.f, a1y = 0.f, f1x = 0.f, f1y = 0.f;

    float4 rb[2][3];
    float4 gtb[2];
    float  hb[2] = {0.f, 0.f};
    float  cb[2] = {0.f, 0.f};

    auto prefetch = [&](int it, int slot) {
        if (it < RPW) {
            const int row = wg + it * (GRID * WARPS);
            const float4* rp = (const float4*)(reg + (size_t)row * 360);
            rb[slot][0] = rp[lane];
            rb[slot][1] = rp[lane + 32];
            if (lane < 26) rb[slot][2] = rp[lane + 64];
            if (lane < 15) gtb[slot] = ((const float4*)(gt + (size_t)row * 60))[lane];
            if (lane < NP) {
                size_t hidx = (size_t)row * NP + lane;
                if (hmode == 0)      hb[slot] = ((const unsigned char*)has)[hidx] ? 1.f : 0.f;
                else if (hmode == 1) hb[slot] = ((const int*)has)[hidx] ? 1.f : 0.f;
                else                 hb[slot] = (((const float*)has)[hidx] != 0.f) ? 1.f : 0.f;
            }
            if (lane < NM) cb[slot] = cls[(size_t)row * NM + lane];
        }
    };

    prefetch(0, 0);

#pragma unroll 2
    for (int it = 0; it < RPW; ++it) {
        const int slot = it & 1;
        // issue next row's loads first — full iteration of work to hide latency
        prefetch(it + 1, slot ^ 1);

        SmBuf& S = sb[warp][slot];

        // stage gt + hasw to smem
        if (lane < 15) ((float4*)S.gt)[lane] = gtb[slot];
        const float hv = (lane < NP) ? hb[slot] : 0.f;
        if (lane < NP) S.hasw[lane] = hv;

        // last index / valid (register-only reduction)
        float lastv = (lane < NP) ? hv + (0.1f * (float)lane) / 30.0f : -1e30f;
        int   lidx  = (lane < NP) ? lane : 1000;
        {
            float mv = lastv; int mi = lidx;
#pragma unroll
            for (int o = 16; o; o >>= 1) {
                float v2 = __shfl_xor_sync(0xffffffffu, mv, o);
                int   i2 = __shfl_xor_sync(0xffffffffu, mi, o);
                if (v2 > mv || (v2 == mv && i2 < mi)) { mv = v2; mi = i2; }
            }
            lidx = mi; lastv = mv;
        }
        const int   last   = lidx;
        const bool  valid  = lastv > 1.0f;
        const float validf = valid ? 1.0f : 0.0f;

        unsigned bal = __ballot_sync(0xffffffffu, (lane < NP) && (hv > 0.f));
        if (lane == 0) a_numreg += validf * (float)__popc(bal);

        __syncwarp();   // gt visible

        // moving flag
        const float mdx = S.gt[0] - S.gt[58], mdy = S.gt[1] - S.gt[59];
        const bool moving = sqrtf(mdx * mdx + mdy * mdy) > 2.0f;

        // trig-free heading: lane t computes cos/sin(theta_t)
        if (lane < NP) {
            float ct = 1.f, st = 0.f;
            if (moving) {
                auto unitf = [&](int j, float& c, float& s, bool& za) {
                    float dx = S.gt[2 * j + 2] - S.gt[2 * j];
                    float dy = S.gt[2 * j + 3] - S.gt[2 * j + 1];
                    float rr = dx * dx + dy * dy;
                    za = (dy == 0.0f) && (dx >= 0.0f);
                    if (rr == 0.f) { c = 1.f; s = 0.f; }
                    else { float inv = rsqrtf(rr); c = dx * inv; s = dy * inv; }
                };
                if (lane == 0) {
                    float c, s; bool za; unitf(0, c, s, za);
                    ct = c; st = -s;
                } else if (lane == NP - 1) {
                    float c, s; bool za; unitf(NP - 2, c, s, za);
                    ct = c; st = -s;
                } else {
                    float ca, sa, cb2, sb2; bool za, zb;
                    unitf(lane,     ca,  sa,  za);
                    unitf(lane - 1, cb2, sb2, zb);
                    if (za || zb) {
                        ct = ca * cb2 - sa * sb2;
                        st = -(sa * cb2 + ca * sb2);
                    } else {
                        float hx = ca + cb2, hy = sa + sb2;
                        float dxx = ca - cb2, dyy = sa - sb2;
                        float h2 = hx * hx + hy * hy;
                        float d2 = dxx * dxx + dyy * dyy;
                        if (h2 >= d2) {
                            float inv = rsqrtf(h2);
                            ct = hx * inv; st = -(hy * inv);
                        } else {
                            float inv = rsqrtf(d2);
                            ct = dyy * inv; st = dxx * inv;
                        }
                    }
                }
            }
            S.cosv[lane] = ct;
            S.sinv[lane] = st;
        }

        // per-mode last-point distance: the lane owning pair (m, last) writes it
        {
            const float gxl = S.gt[2 * last], gyl = S.gt[2 * last + 1];
#pragma unroll
            for (int k = 0; k < 6; k++) {
                if (pv[k] && tk[k] == last) {
                    const float4 f = rb[slot][k >> 1];
                    float rx = (k & 1) ? f.z : f.x;
                    float ry = (k & 1) ? f.w : f.y;
                    float ddx = rx - gxl, ddy = ry - gyl;
                    sdist[warp][mk[k]] = sqrtf(ddx * ddx + ddy * ddy);
                }
            }
        }
        __syncwarp();   // cos/sin + dist visible

        // min-dist mode + cls argmax
        const float myc  = (lane < NM) ? cb[slot] : -1e30f;
        const float dstm = (lane < NM) ? sdist[warp][lane] : 1e30f;
        int min_idx; float min_dist;
        {
            float dv = dstm; int di = (lane < NM) ? lane : 1000;
#pragma unroll
            for (int o = 16; o; o >>= 1) {
                float v2 = __shfl_xor_sync(0xffffffffu, dv, o);
                int   i2 = __shfl_xor_sync(0xffffffffu, di, o);
                if (v2 < dv || (v2 == dv && i2 < di)) { dv = v2; di = i2; }
            }
            min_idx = di; min_dist = dv;
        }
        int top1;
        {
            float cv = myc; int ci = (lane < NM) ? lane : 1000;
#pragma unroll
            for (int o = 16; o; o >>= 1) {
                float v2 = __shfl_xor_sync(0xffffffffu, cv, o);
                int   i2 = __shfl_xor_sync(0xffffffffu, ci, o);
                if (v2 > cv || (v2 == cv && i2 < ci)) { cv = v2; ci = i2; }
            }
            top1 = ci;
        }
        const float cls_min = __shfl_sync(0xffffffffu, myc, min_idx);
        if (lane < NM) {
            float mgn = cls_min - myc;
            bool m01 = (min_dist < 2.0f) && ((dstm - min_dist) > 0.2f) && valid;
            if (m01 && (mgn < 0.2f)) { a_numcls += 1.0f; a_mgn += mgn; }
        }

        // ---- main sweep: 6 register-resident pairs per lane ----
#pragma unroll
        for (int k = 0; k < 6; k++) {
            if (pv[k]) {
                const float4 f = rb[slot][k >> 1];
                float rx = (k & 1) ? f.z : f.x;
                float ry = (k & 1) ? f.w : f.y;
                const int t = tk[k], m = mk[k];
                float gx = S.gt[2 * t], gy = S.gt[2 * t + 1];
                float dx = fabsf(gx - rx);
                float dy = fabsf(gy - ry);
                float c = S.cosv[t], s = S.sinv[t];
                float ex = fabsf(c * dx - s * dy);
                float ey = fabsf(s * dx + c * dy);
                a6x += ex; a6y += ey;
                if (t == NP - 1) { f6x += ex; f6y += ey; }
                if (m == top1) {
                    a1x += ex; a1y += ey;
                    if (t == NP - 1) { f1x += ex; f1y += ey; }
                }
                if (m == min_idx) {
                    float w = S.hasw[t] * validf;
                    float slx = (dx < 1.f) ? 0.5f * dx * dx : dx - 0.5f;
                    float sly = (dy < 1.f) ? 0.5f * dy * dy : dy - 0.5f;
                    a_regl += (slx + sly) * w;
                }
            }
        }
        // no trailing syncwarp: next iteration writes the other smem buffer
    }

    // ---- reduction: warp -> block shared -> global double atomics ----
    a_numcls = warp_sum(a_numcls);
    a_mgn    = warp_sum(a_mgn);
    a_regl   = warp_sum(a_regl);
    a_numreg = warp_sum(a_numreg);
    a6x = warp_sum(a6x); a6y = warp_sum(a6y);
    f6x = warp_sum(f6x); f6y = warp_sum(f6y);
    a1x = warp_sum(a1x); a1y = warp_sum(a1y);
    f1x = warp_sum(f1x); f1y = warp_sum(f1y);

    if (lane == 0) {
        atomicAdd(&blk[0],  (double)a_numcls);
        atomicAdd(&blk[1],  (double)a_mgn);
        atomicAdd(&blk[2],  (double)a_regl);
        atomicAdd(&blk[3],  (double)a_numreg);
        atomicAdd(&blk[4],  (double)a6x);
        atomicAdd(&blk[5],  (double)a6y);
        atomicAdd(&blk[6],  (double)f6x);
        atomicAdd(&blk[7],  (double)f6y);
        atomicAdd(&blk[8],  (double)a1x);
        atomicAdd(&blk[9],  (double)a1y);
        atomicAdd(&blk[10], (double)f1x);
        atomicAdd(&blk[11], (double)f1y);
    }
    __syncthreads();
    if (threadIdx.x < 12) {
        atomicAdd(&g_acc[threadIdx.x], blk[threadIdx.x]);
        __threadfence();
    }
    __syncthreads();

    // last-block finalize (deterministic; resets state for next graph replay)
    if (threadIdx.x == 0) {
        unsigned done = atomicAdd(&g_done, 1u);
        if (done == GRID - 1) {
            __threadfence();
            double acc[12];
#pragma unroll
            for (int i = 0; i < 12; i++) acc[i] = *((volatile double*)&g_acc[i]);

            double num_cls  = acc[0];
            double mgn_sum  = acc[1];
            double reg_loss = acc[2];
            double num_reg  = acc[3];
            double cls_loss = 0.2 * num_cls - mgn_sum;
            double loss = cls_loss / (num_cls + 1e-10) + reg_loss / (num_reg + 1e-10);
            out[0]  = (float)loss;
            out[1]  = (float)cls_loss;
            out[2]  = (float)num_cls;
            out[3]  = (float)reg_loss;
            out[4]  = (float)num_reg;
            out[5]  = (float)acc[4];
            out[6]  = (float)acc[5];
            out[7]  = (float)acc[6];
            out[8]  = (float)acc[7];
            out[9]  = (float)(6.0 * (double)B_ROWS * 30.0);
            out[10] = (float)(6.0 * (double)B_ROWS);
            out[11] = (float)acc[8];
            out[12] = (float)acc[9];
            out[13] = (float)acc[10];
            out[14] = (float)acc[11];
            out[15] = (float)((double)B_ROWS * 30.0);
            out[16] = (float)B_ROWS;

            // reset for next replay
#pragma unroll
            for (int i = 0; i < 12; i++) *((volatile double*)&g_acc[i]) = 0.0;
            __threadfence();
            atomicExch(&g_done, 0u);
        }
    }
}

extern "C" void kernel_launch(void* const* d_in, const int* in_sizes, int n_in,
                              void* d_out, int out_size) {
    // Map inputs by element count (robust to metadata ordering)
    const float* reg = nullptr;
    const float* cls = nullptr;
    const float* gt  = nullptr;
    const void*  has = nullptr;
    for (int i = 0; i < n_in; i++) {
        long long n = in_sizes[i];
        if (n == (long long)B_ROWS * NM * NP * 2)      reg = (const float*)d_in[i];
        else if (n == (long long)B_ROWS * NP * 2)      gt  = (const float*)d_in[i];
        else if (n == (long long)B_ROWS * NP)          has = d_in[i];
        else if (n == (long long)B_ROWS * NM)          cls = (const float*)d_in[i];
    }
    float* out = (float*)d_out;

    loss_main<<<GRID, 256>>>(reg, cls, gt, has, out);
}

// round 4
// speedup vs baseline: 2.0964x; 2.0709x over previous
#include <cuda_runtime.h>
#include <math.h>
#include <stdint.h>

#define B_ROWS   131072
#define NM       6
#define NP       30
#define WARPS    8
#define GRID     2048
#define RPW      (B_ROWS / (GRID * WARPS))   // 8 rows per warp
#define STRIDE   (GRID * WARPS)

// 0 num_cls, 1 mgn_sum, 2 reg_loss, 3 num_reg,
// 4 a6x, 5 a6y, 6 f6x, 7 f6y, 8 a1x, 9 a1y, 10 f1x, 11 f1y
__device__ double g_acc[12];
__device__ unsigned int g_done;

struct __align__(16) Stage {
    float reg[360];   // 1440 B: one row of reg [6,30,2]
    float gt[64];     // 256 B: 60 used
};

__device__ __forceinline__ float warp_sum(float v) {
#pragma unroll
    for (int o = 16; o; o >>= 1) v += __shfl_xor_sync(0xffffffffu, v, o);
    return v;
}

__device__ __forceinline__ void cp16(uint32_t dst, const void* src) {
    asm volatile("cp.async.cg.shared.global [%0], [%1], 16;\n" :: "r"(dst), "l"(src));
}
__device__ __forceinline__ void cp_commit() {
    asm volatile("cp.async.commit_group;\n" ::: "memory");
}
__device__ __forceinline__ void cp_wait1() {
    asm volatile("cp.async.wait_group 1;\n" ::: "memory");
}

__global__ void __launch_bounds__(256) loss_main(
    const float* __restrict__ reg,
    const float* __restrict__ cls,
    const float* __restrict__ gt,
    const void*  __restrict__ has,
    float* __restrict__ out)
{
    __shared__ Stage st[WARPS][2];
    __shared__ double blk[12];

    const int lane = threadIdx.x & 31;
    const int warp = threadIdx.x >> 5;
    if (threadIdx.x < 12) blk[threadIdx.x] = 0.0;
    __syncthreads();

    // detect storage width of bool array `has`
    const unsigned w0 = *((const unsigned*)has);
    const int hmode = (w0 == 0x3F800000u) ? 2 : ((w0 == 1u) ? 1 : 0);

    const int wg = blockIdx.x * WARPS + warp;

    // per-lane partials
    float a_numcls = 0.f, a_mgn = 0.f, a_regl = 0.f, a_numreg = 0.f;
    float a6x = 0.f, a6y = 0.f, f6x = 0.f, f6y = 0.f;
    float a1x = 0.f, a1y = 0.f, f1x = 0.f, f1y = 0.f;

    float hb[2] = {0.f, 0.f};
    float cb[2] = {0.f, 0.f};

    const uint32_t sbase0 = (uint32_t)__cvta_generic_to_shared(&st[warp][0]);
    const uint32_t sbase1 = (uint32_t)__cvta_generic_to_shared(&st[warp][1]);

    auto prefetch = [&](int it, int slot) {
        if (it < RPW) {
            const int row = wg + it * STRIDE;
            const uint32_t sb = slot ? sbase1 : sbase0;
            const char* rsrc = (const char*)(reg + (size_t)row * 360);
            cp16(sb + lane * 16,          rsrc + lane * 16);
            cp16(sb + (lane + 32) * 16,   rsrc + (lane + 32) * 16);
            if (lane < 26)
                cp16(sb + (lane + 64) * 16, rsrc + (lane + 64) * 16);
            if (lane < 15)
                cp16(sb + 1440 + lane * 16,
                     (const char*)(gt + (size_t)row * 60) + lane * 16);
            if (lane < NP) {
                size_t hidx = (size_t)row * NP + lane;
                if (hmode == 0)      hb[slot] = ((const unsigned char*)has)[hidx] ? 1.f : 0.f;
                else if (hmode == 1) hb[slot] = ((const int*)has)[hidx] ? 1.f : 0.f;
                else                 hb[slot] = (((const float*)has)[hidx] != 0.f) ? 1.f : 0.f;
            }
            if (lane < NM) cb[slot] = cls[(size_t)row * NM + lane];
        }
        cp_commit();
    };

    prefetch(0, 0);

#pragma unroll 2
    for (int it = 0; it < RPW; ++it) {
        const int slot = it & 1;
        prefetch(it + 1, slot ^ 1);      // overlap next row's loads
        cp_wait1();                      // all but newest group done
        __syncwarp();

        Stage& S = st[warp][slot];

        // ---- has / last index / valid (ballot + clz) ----
        const float hv = (lane < NP) ? hb[slot] : 0.f;
        const unsigned bal = __ballot_sync(0xffffffffu, (lane < NP) && (hv > 0.f));
        const int  last   = bal ? (31 - __clz(bal)) : (NP - 1);
        const bool valid  = (bal != 0u);
        const float validf = valid ? 1.0f : 0.0f;
        if (lane == 0) a_numreg += validf * (float)__popc(bal);

        // ---- gt point for this lane's timestep (t = lane) ----
        float2 gv = *(float2*)&S.gt[2 * lane];       // lanes 30,31: padding (unused)
        const float gx = gv.x, gy = gv.y;

        // moving flag (from lanes 0 and 29)
        const float g0x = __shfl_sync(0xffffffffu, gx, 0);
        const float g0y = __shfl_sync(0xffffffffu, gy, 0);
        const float gLx = __shfl_sync(0xffffffffu, gx, NP - 1);
        const float gLy = __shfl_sync(0xffffffffu, gy, NP - 1);
        const float mdx = g0x - gLx, mdy = g0y - gLy;
        const bool moving = sqrtf(mdx * mdx + mdy * mdy) > 2.0f;

        // ---- heading: lane t owns cos/sin(theta_t), trig-free ----
        // fwd segment of lane t: gt[t+1] - gt[t]
        const float gnx = __shfl_down_sync(0xffffffffu, gx, 1);
        const float gny = __shfl_down_sync(0xffffffffu, gy, 1);
        float cf = 1.f, sf = 0.f; int zf = 1;
        if (lane < NP - 1) {
            float dxs = gnx - gx, dys = gny - gy;
            float rr = dxs * dxs + dys * dys;
            zf = (dys == 0.0f) && (dxs >= 0.0f);
            if (rr > 0.f) { float inv = rsqrtf(rr); cf = dxs * inv; sf = dys * inv; }
            else { cf = 1.f; sf = 0.f; }
        }
        const float cbw = __shfl_up_sync(0xffffffffu, cf, 1);
        const float sbw = __shfl_up_sync(0xffffffffu, sf, 1);
        const int   zbw = __shfl_up_sync(0xffffffffu, zf, 1);

        float c = 1.f, s = 0.f;
        if (moving && lane < NP) {
            if (lane == 0)            { c = cf;  s = -sf; }
            else if (lane == NP - 1)  { c = cbw; s = -sbw; }
            else if (zf || zbw) {
                c = cf * cbw - sf * sbw;
                s = -(sf * cbw + cf * sbw);
            } else {
                float hx = cf + cbw, hy = sf + sbw;
                float dxx = cf - cbw, dyy = sf - sbw;
                float h2 = hx * hx + hy * hy;
                float d2 = dxx * dxx + dyy * dyy;
                if (h2 >= d2) { float inv = rsqrtf(h2); c = hx * inv;  s = -(hy * inv); }
                else          { float inv = rsqrtf(d2); c = dyy * inv; s = dxx * inv; }
            }
        }

        // ---- per-mode distance at last point (lanes 0..5, m = lane) ----
        const float gxl = __shfl_sync(0xffffffffu, gx, last);
        const float gyl = __shfl_sync(0xffffffffu, gy, last);
        float dstm = 1e30f, myc = -1e30f;
        if (lane < NM) {
            float2 rl = *(float2*)&S.reg[lane * 60 + 2 * last];
            float ddx = rl.x - gxl, ddy = rl.y - gyl;
            dstm = sqrtf(ddx * ddx + ddy * ddy);
            myc  = cb[slot];
        }

        // ---- fused argmin(dist)/argmax(cls) over 8-lane group ----
        int di = (lane < NM) ? lane : 1000;
        int ci = (lane < NM) ? lane : 1000;
        float dv = dstm, cv = myc;
#pragma unroll
        for (int o = 1; o < 8; o <<= 1) {
            float dv2 = __shfl_xor_sync(0xffffffffu, dv, o);
            int   di2 = __shfl_xor_sync(0xffffffffu, di, o);
            float cv2 = __shfl_xor_sync(0xffffffffu, cv, o);
            int   ci2 = __shfl_xor_sync(0xffffffffu, ci, o);
            if (dv2 < dv || (dv2 == dv && di2 < di)) { dv = dv2; di = di2; }
            if (cv2 > cv || (cv2 == cv && ci2 < ci)) { cv = cv2; ci = ci2; }
        }
        const int   min_idx  = __shfl_sync(0xffffffffu, di, 0);
        const float min_dist = __shfl_sync(0xffffffffu, dv, 0);
        const int   top1     = __shfl_sync(0xffffffffu, ci, 0);
        const float cls_min  = __shfl_sync(0xffffffffu, myc, min_idx);

        if (lane < NM) {
            float mgn = cls_min - myc;
            bool m01 = (min_dist < 2.0f) && ((dstm - min_dist) > 0.2f) && valid;
            if (m01 && (mgn < 0.2f)) { a_numcls += 1.0f; a_mgn += mgn; }
        }

        // ---- main sweep: lane = t, loop over modes; uniform branches ----
        if (lane < NP) {
            const float w = hv * validf;
#pragma unroll
            for (int k = 0; k < NM; k++) {
                float2 rv = *(float2*)&S.reg[k * 60 + 2 * lane];
                float dx = fabsf(gx - rv.x);
                float dy = fabsf(gy - rv.y);
                float ex = fabsf(c * dx - s * dy);
                float ey = fabsf(s * dx + c * dy);
                a6x += ex; a6y += ey;
                if (lane == NP - 1) { f6x += ex; f6y += ey; }
                if (k == top1) {                       // warp-uniform
                    a1x += ex; a1y += ey;
                    if (lane == NP - 1) { f1x += ex; f1y += ey; }
                }
                if (k == min_idx) {                    // warp-uniform
                    float slx = (dx < 1.f) ? 0.5f * dx * dx : dx - 0.5f;
                    float sly = (dy < 1.f) ? 0.5f * dy * dy : dy - 0.5f;
                    a_regl += (slx + sly) * w;
                }
            }
        }
        __syncwarp();   // WAR: next iter's cp.async rewrites this buffer
    }

    // ---- reduction ----
    a_numcls = warp_sum(a_numcls);
    a_mgn    = warp_sum(a_mgn);
    a_regl   = warp_sum(a_regl);
    a_numreg = warp_sum(a_numreg);
    a6x = warp_sum(a6x); a6y = warp_sum(a6y);
    f6x = warp_sum(f6x); f6y = warp_sum(f6y);
    a1x = warp_sum(a1x); a1y = warp_sum(a1y);
    f1x = warp_sum(f1x); f1y = warp_sum(f1y);

    if (lane == 0) {
        atomicAdd(&blk[0],  (double)a_numcls);
        atomicAdd(&blk[1],  (double)a_mgn);
        atomicAdd(&blk[2],  (double)a_regl);
        atomicAdd(&blk[3],  (double)a_numreg);
        atomicAdd(&blk[4],  (double)a6x);
        atomicAdd(&blk[5],  (double)a6y);
        atomicAdd(&blk[6],  (double)f6x);
        atomicAdd(&blk[7],  (double)f6y);
        atomicAdd(&blk[8],  (double)a1x);
        atomicAdd(&blk[9],  (double)a1y);
        atomicAdd(&blk[10], (double)f1x);
        atomicAdd(&blk[11], (double)f1y);
    }
    __syncthreads();
    if (threadIdx.x < 12) {
        atomicAdd(&g_acc[threadIdx.x], blk[threadIdx.x]);
        __threadfence();
    }
    __syncthreads();

    if (threadIdx.x == 0) {
        unsigned done = atomicAdd(&g_done, 1u);
        if (done == GRID - 1) {
            __threadfence();
            double acc[12];
#pragma unroll
            for (int i = 0; i < 12; i++) acc[i] = *((volatile double*)&g_acc[i]);

            double num_cls  = acc[0];
            double mgn_sum  = acc[1];
            double reg_loss = acc[2];
            double num_reg  = acc[3];
            double cls_loss = 0.2 * num_cls - mgn_sum;
            double loss = cls_loss / (num_cls + 1e-10) + reg_loss / (num_reg + 1e-10);
            out[0]  = (float)loss;
            out[1]  = (float)cls_loss;
            out[2]  = (float)num_cls;
            out[3]  = (float)reg_loss;
            out[4]  = (float)num_reg;
            out[5]  = (float)acc[4];
            out[6]  = (float)acc[5];
            out[7]  = (float)acc[6];
            out[8]  = (float)acc[7];
            out[9]  = (float)(6.0 * (double)B_ROWS * 30.0);
            out[10] = (float)(6.0 * (double)B_ROWS);
            out[11] = (float)acc[8];
            out[12] = (float)acc[9];
            out[13] = (float)acc[10];
            out[14] = (float)acc[11];
            out[15] = (float)((double)B_ROWS * 30.0);
            out[16] = (float)B_ROWS;

#pragma unroll
            for (int i = 0; i < 12; i++) *((volatile double*)&g_acc[i]) = 0.0;
            __threadfence();
            atomicExch(&g_done, 0u);
        }
    }
}

extern "C" void kernel_launch(void* const* d_in, const int* in_sizes, int n_in,
                              void* d_out, int out_size) {
    const float* reg = nullptr;
    const float* cls = nullptr;
    const float* gt  = nullptr;
    const void*  has = nullptr;
    for (int i = 0; i < n_in; i++) {
        long long n = in_sizes[i];
        if (n == (long long)B_ROWS * NM * NP * 2)      reg = (const float*)d_in[i];
        else if (n == (long long)B_ROWS * NP * 2)      gt  = (const float*)d_in[i];
        else if (n == (long long)B_ROWS * NP)          has = d_in[i];
        else if (n == (long long)B_ROWS * NM)          cls = (const float*)d_in[i];
    }
    float* out = (float*)d_out;

    loss_main<<<GRID, 256>>>(reg, cls, gt, has, out);
}